// round 2
// baseline (speedup 1.0000x reference)
#include <cuda_runtime.h>
#include <cstdint>

#define B_DIM   1024
#define S_DIM   128
#define H_DIM   1024
#define V_DIM   50000
#define COPY_IDX 4
#define PAD_IDX  0
#define EPS_F    1e-10f

// ---------------- scratch (static device allocations only) ----------------
__device__ float  g_logits[(size_t)B_DIM * V_DIM];   // 204.8 MB
__device__ float4 g_stats[B_DIM];                    // {rowmax, 1/Z, copy, 1/norm}
__device__ int    g_tgt[B_DIM * S_DIM];
__device__ float  g_addval[B_DIM * S_DIM];

// ---------------- helpers ----------------
__device__ __forceinline__ uint32_t f2tf32(float x) {
    uint32_t r;
    asm("cvt.rna.tf32.f32 %0, %1;" : "=r"(r) : "f"(x));
    return r;
}

__device__ __forceinline__ void mma_tf32(float* d, const uint32_t* a, const uint32_t* b) {
    asm volatile(
        "mma.sync.aligned.m16n8k8.row.col.f32.tf32.tf32.f32 "
        "{%0,%1,%2,%3},{%4,%5,%6,%7},{%8,%9},{%0,%1,%2,%3};\n"
        : "+f"(d[0]), "+f"(d[1]), "+f"(d[2]), "+f"(d[3])
        : "r"(a[0]), "r"(a[1]), "r"(a[2]), "r"(a[3]), "r"(b[0]), "r"(b[1]));
}

// dtype sniffing: int64 data with values < 2^31 has all odd 32-bit words == 0.
// For genuinely-int32 random data in [0, 50000), P(16 odd words all zero) ~ 50000^-16.
__device__ __forceinline__ bool detect_i64(const int* p) {
    bool z = true;
#pragma unroll
    for (int i = 1; i < 32; i += 2) z = z && (p[i] == 0);
    return z;
}

// ---------------- K1: GEMM  logits = hidden @ W^T + b ----------------
// Block tile 128(M) x 128(N) x 16(K). 256 threads = 8 warps, warp grid 2(M) x 4(N),
// warp tile 64x32 -> 4 m16 tiles x 4 n8 tiles. Smem stride 20 floats (conflict-free
// for the m16n8k8 fragment pattern). Double-buffered smem with register-staged LDG.
#define LDS_STRIDE 20

__global__ void __launch_bounds__(256, 2)
gemm_tf32_kernel(const float* __restrict__ hidden,
                 const float* __restrict__ W,
                 const float* __restrict__ bias)
{
    __shared__ float As[2][128 * LDS_STRIDE];
    __shared__ float Bs[2][128 * LDS_STRIDE];

    const int tid   = threadIdx.x;
    const int lane  = tid & 31;
    const int wid   = tid >> 5;
    const int warpM = wid & 1;       // 0..1
    const int warpN = wid >> 1;      // 0..3
    const int r     = lane >> 2;     // 0..7
    const int cq    = lane & 3;      // 0..3

    const int mBlk = blockIdx.x * 128;   // x fastest => M-blocks of one N-column together (W L2 reuse)
    const int nBlk = blockIdx.y * 128;

    // staging indices: 512 float4 per tile, 2 per thread
    const int i0 = tid,        i1 = tid + 256;
    const int rowT0 = i0 >> 2, colT0 = (i0 & 3) << 2;
    const int rowT1 = i1 >> 2, colT1 = (i1 & 3) << 2;

    const float* gA0 = hidden + (size_t)(mBlk + rowT0) * H_DIM + colT0;
    const float* gA1 = hidden + (size_t)(mBlk + rowT1) * H_DIM + colT1;
    const int nRow0 = nBlk + rowT0;
    const int nRow1 = nBlk + rowT1;
    const float* gB0 = W + (size_t)nRow0 * H_DIM + colT0;
    const float* gB1 = W + (size_t)nRow1 * H_DIM + colT1;
    const bool v0ok = (nRow0 < V_DIM);
    const bool v1ok = (nRow1 < V_DIM);

    float acc[4][4][4];
#pragma unroll
    for (int i = 0; i < 4; ++i)
#pragma unroll
        for (int j = 0; j < 4; ++j)
#pragma unroll
            for (int k = 0; k < 4; ++k) acc[i][j][k] = 0.f;

    const float4 z4 = make_float4(0.f, 0.f, 0.f, 0.f);
    float4 ra0, ra1, rb0, rb1;

    // prefetch kb = 0
    ra0 = *(const float4*)(gA0);
    ra1 = *(const float4*)(gA1);
    rb0 = v0ok ? *(const float4*)(gB0) : z4;
    rb1 = v1ok ? *(const float4*)(gB1) : z4;

    // store (with tf32 rounding) into buffer 0
    {
        float4 t;
        t.x = __uint_as_float(f2tf32(ra0.x)); t.y = __uint_as_float(f2tf32(ra0.y));
        t.z = __uint_as_float(f2tf32(ra0.z)); t.w = __uint_as_float(f2tf32(ra0.w));
        *(float4*)&As[0][rowT0 * LDS_STRIDE + colT0] = t;
        t.x = __uint_as_float(f2tf32(ra1.x)); t.y = __uint_as_float(f2tf32(ra1.y));
        t.z = __uint_as_float(f2tf32(ra1.z)); t.w = __uint_as_float(f2tf32(ra1.w));
        *(float4*)&As[0][rowT1 * LDS_STRIDE + colT1] = t;
        t.x = __uint_as_float(f2tf32(rb0.x)); t.y = __uint_as_float(f2tf32(rb0.y));
        t.z = __uint_as_float(f2tf32(rb0.z)); t.w = __uint_as_float(f2tf32(rb0.w));
        *(float4*)&Bs[0][rowT0 * LDS_STRIDE + colT0] = t;
        t.x = __uint_as_float(f2tf32(rb1.x)); t.y = __uint_as_float(f2tf32(rb1.y));
        t.z = __uint_as_float(f2tf32(rb1.z)); t.w = __uint_as_float(f2tf32(rb1.w));
        *(float4*)&Bs[0][rowT1 * LDS_STRIDE + colT1] = t;
    }

    const int KB = H_DIM / 16;  // 64
    for (int kb = 0; kb < KB; ++kb) {
        __syncthreads();
        const int buf = kb & 1;

        if (kb < KB - 1) {
            const int koff = (kb + 1) * 16;
            ra0 = *(const float4*)(gA0 + koff);
            ra1 = *(const float4*)(gA1 + koff);
            rb0 = v0ok ? *(const float4*)(gB0 + koff) : z4;
            rb1 = v1ok ? *(const float4*)(gB1 + koff) : z4;
        }

#pragma unroll
        for (int ks = 0; ks < 2; ++ks) {
            const int k0 = ks * 8 + cq;
            uint32_t afr[4][4];
            uint32_t bfr[4][2];
#pragma unroll
            for (int mt = 0; mt < 4; ++mt) {
                const float* pa = &As[buf][(warpM * 64 + mt * 16 + r) * LDS_STRIDE + k0];
                afr[mt][0] = __float_as_uint(pa[0]);
                afr[mt][1] = __float_as_uint(pa[8 * LDS_STRIDE]);
                afr[mt][2] = __float_as_uint(pa[4]);
                afr[mt][3] = __float_as_uint(pa[8 * LDS_STRIDE + 4]);
            }
#pragma unroll
            for (int nt = 0; nt < 4; ++nt) {
                const float* pb = &Bs[buf][(warpN * 32 + nt * 8 + r) * LDS_STRIDE + k0];
                bfr[nt][0] = __float_as_uint(pb[0]);
                bfr[nt][1] = __float_as_uint(pb[4]);
            }
#pragma unroll
            for (int mt = 0; mt < 4; ++mt)
#pragma unroll
                for (int nt = 0; nt < 4; ++nt)
                    mma_tf32(acc[mt][nt], afr[mt], bfr[nt]);
        }

        if (kb < KB - 1) {
            const int nb = (kb + 1) & 1;
            float4 t;
            t.x = __uint_as_float(f2tf32(ra0.x)); t.y = __uint_as_float(f2tf32(ra0.y));
            t.z = __uint_as_float(f2tf32(ra0.z)); t.w = __uint_as_float(f2tf32(ra0.w));
            *(float4*)&As[nb][rowT0 * LDS_STRIDE + colT0] = t;
            t.x = __uint_as_float(f2tf32(ra1.x)); t.y = __uint_as_float(f2tf32(ra1.y));
            t.z = __uint_as_float(f2tf32(ra1.z)); t.w = __uint_as_float(f2tf32(ra1.w));
            *(float4*)&As[nb][rowT1 * LDS_STRIDE + colT1] = t;
            t.x = __uint_as_float(f2tf32(rb0.x)); t.y = __uint_as_float(f2tf32(rb0.y));
            t.z = __uint_as_float(f2tf32(rb0.z)); t.w = __uint_as_float(f2tf32(rb0.w));
            *(float4*)&Bs[nb][rowT0 * LDS_STRIDE + colT0] = t;
            t.x = __uint_as_float(f2tf32(rb1.x)); t.y = __uint_as_float(f2tf32(rb1.y));
            t.z = __uint_as_float(f2tf32(rb1.z)); t.w = __uint_as_float(f2tf32(rb1.w));
            *(float4*)&Bs[nb][rowT1 * LDS_STRIDE + colT1] = t;
        }
    }

    // epilogue: add bias, store to g_logits
    const int mW = mBlk + warpM * 64;
    const int nW = nBlk + warpN * 32;
#pragma unroll
    for (int mt = 0; mt < 4; ++mt) {
        const int row = mW + mt * 16 + r;
#pragma unroll
        for (int nt = 0; nt < 4; ++nt) {
            const int col = nW + nt * 8 + 2 * cq;
            float* p0 = &g_logits[(size_t)row * V_DIM + col];
            float* p1 = &g_logits[(size_t)(row + 8) * V_DIM + col];
            if (col + 1 < V_DIM) {
                const float bv0 = bias[col], bv1 = bias[col + 1];
                *(float2*)p0 = make_float2(acc[mt][nt][0] + bv0, acc[mt][nt][1] + bv1);
                *(float2*)p1 = make_float2(acc[mt][nt][2] + bv0, acc[mt][nt][3] + bv1);
            } else if (col < V_DIM) {
                const float bv0 = bias[col];
                p0[0] = acc[mt][nt][0] + bv0;
                p1[0] = acc[mt][nt][2] + bv0;
            }
        }
    }
}

// ---------------- K2: per-row stats ----------------
__global__ void __launch_bounds__(256)
row_stats_kernel(const float* __restrict__ attn,
                 const void* __restrict__ src_raw,
                 const void* __restrict__ alignment_raw)
{
    __shared__ float red[256];
    const int b   = blockIdx.x;
    const int tid = threadIdx.x;
    const float* lrow = g_logits + (size_t)b * V_DIM;

    // max over modified logits
    float m = -1e30f;
    for (int i = tid; i < V_DIM; i += 256) {
        float l = (i == COPY_IDX) ? 1e-10f : lrow[i];
        m = fmaxf(m, l);
    }
    red[tid] = m; __syncthreads();
    for (int s = 128; s > 0; s >>= 1) {
        if (tid < s) red[tid] = fmaxf(red[tid], red[tid + s]);
        __syncthreads();
    }
    const float M = red[0];
    __syncthreads();

    // sum exp
    float sm = 0.f;
    for (int i = tid; i < V_DIM; i += 256) {
        float l = (i == COPY_IDX) ? 1e-10f : lrow[i];
        sm += __expf(l - M);
    }
    red[tid] = sm; __syncthreads();
    for (int s = 128; s > 0; s >>= 1) {
        if (tid < s) red[tid] += red[tid + s];
        __syncthreads();
    }
    const float Z = red[0];
    __syncthreads();

    const float copy = 1.f / (1.f + __expf(-lrow[COPY_IDX]));

    // dtype-sniff src / alignment (int32 vs int64)
    const bool src64 = detect_i64((const int*)src_raw);
    const bool aln64 = detect_i64((const int*)alignment_raw);

    // gather alignment[src], attn sums
    float av = 0.f, a0 = 0.f;
    if (tid < S_DIM) {
        const size_t sidx = (size_t)b * S_DIM + tid;
        long long sv;
        if (src64) sv = ((const long long*)src_raw)[sidx];
        else       sv = (long long)((const int*)src_raw)[sidx];
        int tg;
        if (aln64) tg = (int)((const long long*)alignment_raw)[sv];
        else       tg = ((const int*)alignment_raw)[sv];
        g_tgt[b * S_DIM + tid] = tg;
        const float a = attn[sidx];
        g_addval[b * S_DIM + tid] = a * copy;
        av = a;
        a0 = (tg == PAD_IDX) ? a : 0.f;
    }
    red[tid] = av; __syncthreads();
    for (int s = 128; s > 0; s >>= 1) {
        if (tid < s) red[tid] += red[tid + s];
        __syncthreads();
    }
    const float sumattn = red[0];
    __syncthreads();
    red[tid] = a0; __syncthreads();
    for (int s = 128; s > 0; s >>= 1) {
        if (tid < s) red[tid] += red[tid + s];
        __syncthreads();
    }
    const float scat0 = red[0];

    if (tid == 0) {
        // norm = sum of out_prob after scatter and PAD replacement
        const float prepad = (1.f - copy) * __expf(lrow[PAD_IDX] - M) / Z + copy * scat0;
        const float norm = (1.f - copy) + copy * sumattn - prepad + EPS_F;
        g_stats[b] = make_float4(M, 1.f / Z, copy, 1.f / norm);
    }
}

// ---------------- K3: final probs + scatter + log ----------------
#define CHUNK 2048

__global__ void __launch_bounds__(256)
final_kernel(float* __restrict__ out)
{
    __shared__ float sp[CHUNK];
    const int b   = blockIdx.x;
    const int v0  = blockIdx.y * CHUNK;
    const int tid = threadIdx.x;

    const float4 st = g_stats[b];
    const float M = st.x, invZ = st.y, copy = st.z, invnorm = st.w;
    const float scale = (1.f - copy) * invZ;
    const float* lrow = g_logits + (size_t)b * V_DIM;

#pragma unroll
    for (int j = 0; j < CHUNK / 256; ++j) {
        const int v = v0 + tid + j * 256;
        if (v < V_DIM) {
            const float l = (v == COPY_IDX) ? 1e-10f : lrow[v];
            sp[v - v0] = scale * __expf(l - M);
        }
    }
    __syncthreads();

    if (tid < S_DIM) {
        const int tg  = g_tgt[b * S_DIM + tid];
        const int off = tg - v0;
        if (off >= 0 && off < CHUNK)
            atomicAdd(&sp[off], g_addval[b * S_DIM + tid]);
    }
    __syncthreads();

#pragma unroll
    for (int j = 0; j < CHUNK / 256; ++j) {
        const int v = v0 + tid + j * 256;
        if (v < V_DIM) {
            const float p = (v == PAD_IDX) ? EPS_F : sp[v - v0];
            out[(size_t)b * V_DIM + v] = __logf(p * invnorm + EPS_F);
        }
    }
}

// ---------------- launch ----------------
extern "C" void kernel_launch(void* const* d_in, const int* in_sizes, int n_in,
                              void* d_out, int out_size)
{
    const float* hidden    = (const float*)d_in[0];
    const void*  src       = d_in[1];
    const float* attn      = (const float*)d_in[2];
    const float* W         = (const float*)d_in[3];
    const float* bias      = (const float*)d_in[4];
    const void*  alignment = d_in[5];
    float*       out       = (float*)d_out;

    dim3 g1(B_DIM / 128, (V_DIM + 127) / 128);   // (8, 391) — M fastest for W reuse
    gemm_tf32_kernel<<<g1, 256>>>(hidden, W, bias);

    row_stats_kernel<<<B_DIM, 256>>>(attn, src, alignment);

    dim3 g3(B_DIM, (V_DIM + CHUNK - 1) / CHUNK); // (1024, 25)
    final_kernel<<<g3, 256>>>(out);
}

// round 4
// speedup vs baseline: 1.2459x; 1.2459x over previous
#include <cuda_runtime.h>
#include <cstdint>

#define B_DIM   1024
#define S_DIM   128
#define H_DIM   1024
#define V_DIM   50000
#define COPY_IDX 4
#define PAD_IDX  0
#define EPS_F    1e-10f

// GEMM tiling: CTA 128(M) x 256(N) x 16(K), 8 warps of 64x64
#define TM 128
#define TN 256
#define NBLKS ((V_DIM + TN - 1) / TN)   // 196
#define PARTS (NBLKS * 4)               // 784 partial sums per row
#define KITERS (H_DIM / 16)             // 64
#define NSTAGE 4

// smem layout in floats
#define SM_BIAS_F 0
#define SM_A_F    256
#define A_STAGE_F (128 * 20)            // 2560
#define SM_B_F    (256 + 4 * A_STAGE_F) // 10496
#define B_STAGE_F (256 * 20)            // 5120
#define SMEM_F    (SM_B_F + 4 * B_STAGE_F)  // 30976 floats
#define SMEM_BYTES (SMEM_F * 4)             // 123904 B

// ---------------- scratch ----------------
__device__ float  g_logits[(size_t)B_DIM * V_DIM];    // 204.8 MB
__device__ float  g_partial[(size_t)B_DIM * PARTS];   // 3.2 MB
__device__ float4 g_stats[B_DIM];                     // {0, 1/Z, copy, 1/norm}
__device__ int    g_tgt[B_DIM * S_DIM];
__device__ float  g_addval[B_DIM * S_DIM];

// ---------------- helpers ----------------
__device__ __forceinline__ uint32_t smem_u32(const void* p) {
    uint32_t a;
    asm("{ .reg .u64 t; cvta.to.shared.u64 t, %1; cvt.u32.u64 %0, t; }" : "=r"(a) : "l"(p));
    return a;
}
__device__ __forceinline__ void cp16(uint32_t dst, const void* src, int n) {
    asm volatile("cp.async.cg.shared.global [%0], [%1], 16, %2;\n" :: "r"(dst), "l"(src), "r"(n));
}
__device__ __forceinline__ void mma_tf32(float* d, const uint32_t* a, const uint32_t* b) {
    asm volatile(
        "mma.sync.aligned.m16n8k8.row.col.f32.tf32.tf32.f32 "
        "{%0,%1,%2,%3},{%4,%5,%6,%7},{%8,%9},{%0,%1,%2,%3};\n"
        : "+f"(d[0]), "+f"(d[1]), "+f"(d[2]), "+f"(d[3])
        : "r"(a[0]), "r"(a[1]), "r"(a[2]), "r"(a[3]), "r"(b[0]), "r"(b[1]));
}
// int64-vs-int32 sniffing: int64 values < 2^31 have all odd 32-bit words zero.
__device__ __forceinline__ bool detect_i64(const int* p) {
    bool z = true;
#pragma unroll
    for (int i = 1; i < 32; i += 2) z = z && (p[i] == 0);
    return z;
}

// ---------------- K1: tf32 mma GEMM + fused exp row-partials ----------------
__device__ __forceinline__ void load_stage(uint32_t a_u32, uint32_t b_u32,
                                           const float* __restrict__ hidden,
                                           const float* __restrict__ W,
                                           int mBlk, int nBlk, int k0, int tid)
{
#pragma unroll
    for (int j = 0; j < 6; ++j) {
        const int t = tid + j * 256;
        if (t < 512) {                       // A: 128 rows x 4 float4
            const int row = t >> 2, q = t & 3;
            const float* src = hidden + (size_t)(mBlk + row) * H_DIM + k0 + q * 4;
            cp16(a_u32 + (row * 20 + q * 4) * 4, src, 16);
        } else {                             // B: 256 rows x 4 float4
            const int t2 = t - 512;
            const int row = t2 >> 2, q = t2 & 3;
            const int gn = nBlk + row;
            const int ok = (gn < V_DIM) ? 16 : 0;
            const float* src = W + (size_t)(ok ? gn : 0) * H_DIM + k0 + q * 4;
            cp16(b_u32 + (row * 20 + q * 4) * 4, src, ok);
        }
    }
}

__global__ void __launch_bounds__(256, 1)
gemm_kernel(const float* __restrict__ hidden,
            const float* __restrict__ W,
            const float* __restrict__ bias)
{
    extern __shared__ float smf[];
    const uint32_t sb = smem_u32(smf);

    const int tid   = threadIdx.x;
    const int lane  = tid & 31;
    const int wid   = tid >> 5;
    const int warpM = wid & 1;       // 0..1
    const int warpN = wid >> 1;      // 0..3
    const int r     = lane >> 2;     // 0..7
    const int cq    = lane & 3;      // 0..3

    const int mBlk = blockIdx.x * TM;
    const int nBlk = blockIdx.y * TN;

    // bias preload
    {
        const int c = nBlk + tid;
        smf[SM_BIAS_F + tid] = (c < V_DIM) ? bias[c] : 0.f;
    }

    float acc[4][8][4];
#pragma unroll
    for (int i = 0; i < 4; ++i)
#pragma unroll
        for (int j = 0; j < 8; ++j)
#pragma unroll
            for (int k = 0; k < 4; ++k) acc[i][j][k] = 0.f;

    // prologue: 3 stages
#pragma unroll
    for (int s = 0; s < NSTAGE - 1; ++s) {
        load_stage(sb + (SM_A_F + s * A_STAGE_F) * 4, sb + (SM_B_F + s * B_STAGE_F) * 4,
                   hidden, W, mBlk, nBlk, s * 16, tid);
        asm volatile("cp.async.commit_group;");
    }

    for (int ks = 0; ks < KITERS; ++ks) {
        asm volatile("cp.async.wait_group 2;");
        __syncthreads();

        const float* Ab = smf + SM_A_F + (ks & 3) * A_STAGE_F;
        const float* Bb = smf + SM_B_F + (ks & 3) * B_STAGE_F;

#pragma unroll
        for (int sl = 0; sl < 2; ++sl) {
            const int k0 = sl * 8 + cq;
            uint32_t afr[4][4];
            uint32_t bfr[8][2];
#pragma unroll
            for (int mt = 0; mt < 4; ++mt) {
                const float* pa = Ab + (warpM * 64 + mt * 16 + r) * 20 + k0;
                afr[mt][0] = __float_as_uint(pa[0]);
                afr[mt][1] = __float_as_uint(pa[8 * 20]);
                afr[mt][2] = __float_as_uint(pa[4]);
                afr[mt][3] = __float_as_uint(pa[8 * 20 + 4]);
            }
#pragma unroll
            for (int nt = 0; nt < 8; ++nt) {
                const float* pb = Bb + (warpN * 64 + nt * 8 + r) * 20 + k0;
                bfr[nt][0] = __float_as_uint(pb[0]);
                bfr[nt][1] = __float_as_uint(pb[4]);
            }
#pragma unroll
            for (int mt = 0; mt < 4; ++mt)
#pragma unroll
                for (int nt = 0; nt < 8; ++nt)
                    mma_tf32(acc[mt][nt], afr[mt], bfr[nt]);
        }

        const int tl = ks + NSTAGE - 1;
        if (tl < KITERS) {
            load_stage(sb + (SM_A_F + (tl & 3) * A_STAGE_F) * 4,
                       sb + (SM_B_F + (tl & 3) * B_STAGE_F) * 4,
                       hidden, W, mBlk, nBlk, tl * 16, tid);
        }
        asm volatile("cp.async.commit_group;");
    }

    // epilogue: bias add, store logits, per-row exp partial sums
    const float* bias_s = smf + SM_BIAS_F;
#pragma unroll
    for (int mt = 0; mt < 4; ++mt) {
        const int row0 = mBlk + warpM * 64 + mt * 16 + r;
        float rs0 = 0.f, rs1 = 0.f;
#pragma unroll
        for (int nt = 0; nt < 8; ++nt) {
            const int lc = warpN * 64 + nt * 8 + 2 * cq;
            const int gc = nBlk + lc;
            const float bv0 = bias_s[lc], bv1 = bias_s[lc + 1];
            const float v0 = acc[mt][nt][0] + bv0;
            const float v1 = acc[mt][nt][1] + bv1;
            const float v2 = acc[mt][nt][2] + bv0;
            const float v3 = acc[mt][nt][3] + bv1;
            if (gc < V_DIM) {   // V even, gc even => gc+1 < V too
                *(float2*)&g_logits[(size_t)row0 * V_DIM + gc]       = make_float2(v0, v1);
                *(float2*)&g_logits[(size_t)(row0 + 8) * V_DIM + gc] = make_float2(v2, v3);
                rs0 += __expf(v0) + __expf(v1);
                rs1 += __expf(v2) + __expf(v3);
            }
        }
        rs0 += __shfl_xor_sync(0xFFFFFFFF, rs0, 1);
        rs0 += __shfl_xor_sync(0xFFFFFFFF, rs0, 2);
        rs1 += __shfl_xor_sync(0xFFFFFFFF, rs1, 1);
        rs1 += __shfl_xor_sync(0xFFFFFFFF, rs1, 2);
        if (cq == 0) {
            const int pidx = blockIdx.y * 4 + warpN;
            g_partial[(size_t)row0 * PARTS + pidx]       = rs0;
            g_partial[(size_t)(row0 + 8) * PARTS + pidx] = rs1;
        }
    }
}

// ---------------- K2: stats (partials reduce + gather) ----------------
__global__ void __launch_bounds__(256)
stats_kernel(const float* __restrict__ attn,
             const void* __restrict__ src_raw,
             const void* __restrict__ alignment_raw)
{
    __shared__ float red[256];
    const int b   = blockIdx.x;
    const int tid = threadIdx.x;

    float s = 0.f;
    for (int i = tid; i < PARTS; i += 256) s += g_partial[(size_t)b * PARTS + i];
    red[tid] = s; __syncthreads();
    for (int st = 128; st > 0; st >>= 1) {
        if (tid < st) red[tid] += red[tid + st];
        __syncthreads();
    }
    const float Sraw = red[0];
    __syncthreads();

    const float l4 = g_logits[(size_t)b * V_DIM + COPY_IDX];
    const float Z  = Sraw - __expf(l4) + 1.0f;           // exp(1e-10) == 1.0f
    const float copy = 1.f / (1.f + __expf(-l4));

    const bool src64 = detect_i64((const int*)src_raw);
    const bool aln64 = detect_i64((const int*)alignment_raw);

    float av = 0.f, a0 = 0.f;
    if (tid < S_DIM) {
        const size_t sidx = (size_t)b * S_DIM + tid;
        long long sv;
        if (src64) sv = ((const long long*)src_raw)[sidx];
        else       sv = (long long)((const int*)src_raw)[sidx];
        int tg;
        if (aln64) tg = (int)((const long long*)alignment_raw)[sv];
        else       tg = ((const int*)alignment_raw)[sv];
        g_tgt[b * S_DIM + tid] = tg;
        const float a = attn[sidx];
        g_addval[b * S_DIM + tid] = a * copy;
        av = a;
        a0 = (tg == PAD_IDX) ? a : 0.f;
    }
    red[tid] = av; __syncthreads();
    for (int st = 128; st > 0; st >>= 1) {
        if (tid < st) red[tid] += red[tid + st];
        __syncthreads();
    }
    const float sumattn = red[0];
    __syncthreads();
    red[tid] = a0; __syncthreads();
    for (int st = 128; st > 0; st >>= 1) {
        if (tid < st) red[tid] += red[tid + st];
        __syncthreads();
    }
    const float scat0 = red[0];

    if (tid == 0) {
        const float l0 = g_logits[(size_t)b * V_DIM + PAD_IDX];
        const float prepad = (1.f - copy) * __expf(l0) / Z + copy * scat0;
        const float norm = (1.f - copy) + copy * sumattn - prepad + EPS_F;
        g_stats[b] = make_float4(0.f, 1.f / Z, copy, 1.f / norm);
    }
}

// ---------------- K3: streaming log-prob ----------------
#define K3_SPLIT 8
__global__ void __launch_bounds__(256)
final_stream_kernel(float* __restrict__ out)
{
    const int b = blockIdx.x;
    const float4 st = g_stats[b];
    const float invZ = st.y, copy = st.z, invnorm = st.w;
    const float k = (1.f - copy) * invZ * invnorm;
    const float4* in4 = (const float4*)(g_logits + (size_t)b * V_DIM);
    float4* out4 = (float4*)(out + (size_t)b * V_DIM);
    const int NV4 = V_DIM / 4;                 // 12500
    const int per = (NV4 + K3_SPLIT - 1) / K3_SPLIT;
    const int beg = blockIdx.y * per;
    const int end = (beg + per < NV4) ? beg + per : NV4;
    for (int i = beg + threadIdx.x; i < end; i += 256) {
        float4 v = in4[i];
        if (i == 1) v.x = 1e-10f;              // COPY (index 4)
        float4 r;
        r.x = __logf(k * __expf(v.x) + EPS_F);
        r.y = __logf(k * __expf(v.y) + EPS_F);
        r.z = __logf(k * __expf(v.z) + EPS_F);
        r.w = __logf(k * __expf(v.w) + EPS_F);
        if (i == 0) r.x = __logf(EPS_F * invnorm + EPS_F);   // PAD
        out4[i] = r;
    }
}

// ---------------- K4: scatter fixup (<=128 positions/row, dup-aggregating) --
__global__ void __launch_bounds__(128)
fixup_kernel(float* __restrict__ out)
{
    __shared__ int   stg[S_DIM];
    __shared__ float sad[S_DIM];
    const int b = blockIdx.x, t = threadIdx.x;
    stg[t] = g_tgt[b * S_DIM + t];
    sad[t] = g_addval[b * S_DIM + t];
    __syncthreads();
    const int tg = stg[t];
    if (tg == PAD_IDX) return;
    float tot = 0.f; bool first = true;
    for (int j = 0; j < S_DIM; ++j) {
        if (stg[j] == tg) { tot += sad[j]; if (j < t) first = false; }
    }
    if (!first) return;
    const float4 st = g_stats[b];
    const float l = (tg == COPY_IDX) ? 1e-10f : g_logits[(size_t)b * V_DIM + tg];
    const float p = (1.f - st.z) * st.y * __expf(l) + tot;
    out[(size_t)b * V_DIM + tg] = __logf(p * st.w + EPS_F);
}

// ---------------- launch ----------------
extern "C" void kernel_launch(void* const* d_in, const int* in_sizes, int n_in,
                              void* d_out, int out_size)
{
    const float* hidden    = (const float*)d_in[0];
    const void*  src       = d_in[1];
    const float* attn      = (const float*)d_in[2];
    const float* W         = (const float*)d_in[3];
    const float* bias      = (const float*)d_in[4];
    const void*  alignment = d_in[5];
    float*       out       = (float*)d_out;

    cudaFuncSetAttribute(gemm_kernel, cudaFuncAttributeMaxDynamicSharedMemorySize, SMEM_BYTES);

    dim3 g1(B_DIM / TM, NBLKS);                  // (8, 196) — M fastest for W L2 reuse
    gemm_kernel<<<g1, 256, SMEM_BYTES>>>(hidden, W, bias);

    stats_kernel<<<B_DIM, 256>>>(attn, src, alignment);

    dim3 g3(B_DIM, K3_SPLIT);
    final_stream_kernel<<<g3, 256>>>(out);

    fixup_kernel<<<B_DIM, S_DIM>>>(out);
}

// round 5
// speedup vs baseline: 1.3719x; 1.1012x over previous
#include <cuda_runtime.h>
#include <cstdint>

#define B_DIM   1024
#define S_DIM   128
#define H_DIM   1024
#define V_DIM   50000
#define COPY_IDX 4
#define PAD_IDX  0
#define EPS_F    1e-10f

// GEMM tiling: CTA 128(M) x 256(N) x 16(K), 8 warps of 64x64
#define TM 128
#define TN 256
#define NBLKS ((V_DIM + TN - 1) / TN)   // 196
#define PARTS (NBLKS * 4)               // 784 partial sums per row
#define KITERS (H_DIM / 16)             // 64
#define NSTAGE 4

// smem layout in floats
#define SM_BIAS_F 0
#define SM_A_F    256
#define A_STAGE_F (128 * 20)            // 2560
#define SM_B_F    (256 + 4 * A_STAGE_F) // 10496
#define B_STAGE_F (256 * 20)            // 5120
#define SMEM_F    (SM_B_F + 4 * B_STAGE_F)  // 30976 floats
#define SMEM_BYTES (SMEM_F * 4)             // 123904 B

// ---------------- scratch ----------------
__device__ float  g_logits[(size_t)B_DIM * V_DIM];    // 204.8 MB
__device__ float  g_partial[(size_t)B_DIM * PARTS];   // 3.2 MB
__device__ float4 g_stats[B_DIM];                     // {0, 1/Z, copy, 1/norm}
__device__ int    g_tgt[B_DIM * S_DIM];
__device__ float  g_addval[B_DIM * S_DIM];

// ---------------- helpers ----------------
__device__ __forceinline__ uint32_t smem_u32(const void* p) {
    uint32_t a;
    asm("{ .reg .u64 t; cvta.to.shared.u64 t, %1; cvt.u32.u64 %0, t; }" : "=r"(a) : "l"(p));
    return a;
}
__device__ __forceinline__ void cp16(uint32_t dst, const void* src, int n) {
    asm volatile("cp.async.cg.shared.global [%0], [%1], 16, %2;\n" :: "r"(dst), "l"(src), "r"(n));
}
__device__ __forceinline__ void mma_tf32(float* d, const uint32_t* a, const uint32_t* b) {
    asm volatile(
        "mma.sync.aligned.m16n8k8.row.col.f32.tf32.tf32.f32 "
        "{%0,%1,%2,%3},{%4,%5,%6,%7},{%8,%9},{%0,%1,%2,%3};\n"
        : "+f"(d[0]), "+f"(d[1]), "+f"(d[2]), "+f"(d[3])
        : "r"(a[0]), "r"(a[1]), "r"(a[2]), "r"(a[3]), "r"(b[0]), "r"(b[1]));
}
// ldmatrix: type-agnostic 8x8xb16 mover; one x4 = full tf32 A fragment (m16k8),
// one x2 = full tf32 B fragment (k8n8). Lane l supplies the 16B row address of
// submatrix (l>>3), row (l&7).
__device__ __forceinline__ void ldsm_x4(uint32_t* d, uint32_t a) {
    asm volatile("ldmatrix.sync.aligned.m8n8.x4.shared.b16 {%0,%1,%2,%3}, [%4];"
        : "=r"(d[0]), "=r"(d[1]), "=r"(d[2]), "=r"(d[3]) : "r"(a));
}
__device__ __forceinline__ void ldsm_x2(uint32_t* d, uint32_t a) {
    asm volatile("ldmatrix.sync.aligned.m8n8.x2.shared.b16 {%0,%1}, [%2];"
        : "=r"(d[0]), "=r"(d[1]) : "r"(a));
}
// int64-vs-int32 sniffing: int64 values < 2^31 have all odd 32-bit words zero.
__device__ __forceinline__ bool detect_i64(const int* p) {
    bool z = true;
#pragma unroll
    for (int i = 1; i < 32; i += 2) z = z && (p[i] == 0);
    return z;
}

// ---------------- K1: tf32 mma GEMM + fused exp row-partials ----------------
__device__ __forceinline__ void load_stage(uint32_t a_u32, uint32_t b_u32,
                                           const float* __restrict__ hidden,
                                           const float* __restrict__ W,
                                           int mBlk, int nBlk, int k0, int tid)
{
#pragma unroll
    for (int j = 0; j < 6; ++j) {
        const int t = tid + j * 256;
        if (t < 512) {                       // A: 128 rows x 4 float4
            const int row = t >> 2, q = t & 3;
            const float* src = hidden + (size_t)(mBlk + row) * H_DIM + k0 + q * 4;
            cp16(a_u32 + (row * 20 + q * 4) * 4, src, 16);
        } else {                             // B: 256 rows x 4 float4
            const int t2 = t - 512;
            const int row = t2 >> 2, q = t2 & 3;
            const int gn = nBlk + row;
            const int ok = (gn < V_DIM) ? 16 : 0;
            const float* src = W + (size_t)(ok ? gn : 0) * H_DIM + k0 + q * 4;
            cp16(b_u32 + (row * 20 + q * 4) * 4, src, ok);
        }
    }
}

__global__ void __launch_bounds__(256, 1)
gemm_kernel(const float* __restrict__ hidden,
            const float* __restrict__ W,
            const float* __restrict__ bias)
{
    extern __shared__ float smf[];
    const uint32_t sb = smem_u32(smf);

    const int tid   = threadIdx.x;
    const int lane  = tid & 31;
    const int wid   = tid >> 5;
    const int warpM = wid & 1;       // 0..1
    const int warpN = wid >> 1;      // 0..3
    const int r     = lane >> 2;     // 0..7
    const int cq    = lane & 3;      // 0..3

    const int mBlk = blockIdx.x * TM;
    const int nBlk = blockIdx.y * TN;

    // bias preload
    {
        const int c = nBlk + tid;
        smf[SM_BIAS_F + tid] = (c < V_DIM) ? bias[c] : 0.f;
    }

    // ldmatrix per-lane base addresses (bytes)
    const int l7 = lane & 7;
    const int qa = lane >> 3;              // 0..3 (A x4: submatrix index)
    const int qb = (lane >> 3) & 1;        // 0..1 (B x2)
    const uint32_t aBase = sb + (uint32_t)(SM_A_F +
        (warpM * 64 + (qa & 1) * 8 + l7) * 20 + (qa >> 1) * 4) * 4;
    const uint32_t bBase = sb + (uint32_t)(SM_B_F +
        (warpN * 64 + l7) * 20 + qb * 4) * 4;

    float acc[4][8][4];
#pragma unroll
    for (int i = 0; i < 4; ++i)
#pragma unroll
        for (int j = 0; j < 8; ++j)
#pragma unroll
            for (int k = 0; k < 4; ++k) acc[i][j][k] = 0.f;

    // prologue: 3 stages
#pragma unroll
    for (int s = 0; s < NSTAGE - 1; ++s) {
        load_stage(sb + (SM_A_F + s * A_STAGE_F) * 4, sb + (SM_B_F + s * B_STAGE_F) * 4,
                   hidden, W, mBlk, nBlk, s * 16, tid);
        asm volatile("cp.async.commit_group;");
    }

    for (int ks = 0; ks < KITERS; ++ks) {
        asm volatile("cp.async.wait_group 2;");
        __syncthreads();

        const uint32_t aStage = aBase + (uint32_t)((ks & 3) * A_STAGE_F) * 4;
        const uint32_t bStage = bBase + (uint32_t)((ks & 3) * B_STAGE_F) * 4;

#pragma unroll
        for (int sl = 0; sl < 2; ++sl) {
            uint32_t afr[4][4];
            uint32_t bfr[8][2];
#pragma unroll
            for (int mt = 0; mt < 4; ++mt)
                ldsm_x4(afr[mt], aStage + (uint32_t)(mt * 16 * 20 + sl * 8) * 4);
#pragma unroll
            for (int nt = 0; nt < 8; ++nt)
                ldsm_x2(bfr[nt], bStage + (uint32_t)(nt * 8 * 20 + sl * 8) * 4);
#pragma unroll
            for (int mt = 0; mt < 4; ++mt)
#pragma unroll
                for (int nt = 0; nt < 8; ++nt)
                    mma_tf32(acc[mt][nt], afr[mt], bfr[nt]);
        }

        const int tl = ks + NSTAGE - 1;
        if (tl < KITERS) {
            load_stage(sb + (SM_A_F + (tl & 3) * A_STAGE_F) * 4,
                       sb + (SM_B_F + (tl & 3) * B_STAGE_F) * 4,
                       hidden, W, mBlk, nBlk, tl * 16, tid);
        }
        asm volatile("cp.async.commit_group;");
    }

    // epilogue: bias add, store logits, per-row exp partial sums
    const float* bias_s = smf + SM_BIAS_F;
#pragma unroll
    for (int mt = 0; mt < 4; ++mt) {
        const int row0 = mBlk + warpM * 64 + mt * 16 + r;
        float rs0 = 0.f, rs1 = 0.f;
#pragma unroll
        for (int nt = 0; nt < 8; ++nt) {
            const int lc = warpN * 64 + nt * 8 + 2 * cq;
            const int gc = nBlk + lc;
            const float bv0 = bias_s[lc], bv1 = bias_s[lc + 1];
            const float v0 = acc[mt][nt][0] + bv0;
            const float v1 = acc[mt][nt][1] + bv1;
            const float v2 = acc[mt][nt][2] + bv0;
            const float v3 = acc[mt][nt][3] + bv1;
            if (gc < V_DIM) {   // V even, gc even => gc+1 < V too
                *(float2*)&g_logits[(size_t)row0 * V_DIM + gc]       = make_float2(v0, v1);
                *(float2*)&g_logits[(size_t)(row0 + 8) * V_DIM + gc] = make_float2(v2, v3);
                rs0 += __expf(v0) + __expf(v1);
                rs1 += __expf(v2) + __expf(v3);
            }
        }
        rs0 += __shfl_xor_sync(0xFFFFFFFF, rs0, 1);
        rs0 += __shfl_xor_sync(0xFFFFFFFF, rs0, 2);
        rs1 += __shfl_xor_sync(0xFFFFFFFF, rs1, 1);
        rs1 += __shfl_xor_sync(0xFFFFFFFF, rs1, 2);
        if (cq == 0) {
            const int pidx = blockIdx.y * 4 + warpN;
            g_partial[(size_t)row0 * PARTS + pidx]       = rs0;
            g_partial[(size_t)(row0 + 8) * PARTS + pidx] = rs1;
        }
    }
}

// ---------------- K2: stats (partials reduce + gather) ----------------
__global__ void __launch_bounds__(256)
stats_kernel(const float* __restrict__ attn,
             const void* __restrict__ src_raw,
             const void* __restrict__ alignment_raw)
{
    __shared__ float red[256];
    const int b   = blockIdx.x;
    const int tid = threadIdx.x;

    float s = 0.f;
    for (int i = tid; i < PARTS; i += 256) s += g_partial[(size_t)b * PARTS + i];
    red[tid] = s; __syncthreads();
    for (int st = 128; st > 0; st >>= 1) {
        if (tid < st) red[tid] += red[tid + st];
        __syncthreads();
    }
    const float Sraw = red[0];
    __syncthreads();

    const float l4 = g_logits[(size_t)b * V_DIM + COPY_IDX];
    const float Z  = Sraw - __expf(l4) + 1.0f;           // exp(1e-10) == 1.0f
    const float copy = 1.f / (1.f + __expf(-l4));

    const bool src64 = detect_i64((const int*)src_raw);
    const bool aln64 = detect_i64((const int*)alignment_raw);

    float av = 0.f, a0 = 0.f;
    if (tid < S_DIM) {
        const size_t sidx = (size_t)b * S_DIM + tid;
        long long sv;
        if (src64) sv = ((const long long*)src_raw)[sidx];
        else       sv = (long long)((const int*)src_raw)[sidx];
        int tg;
        if (aln64) tg = (int)((const long long*)alignment_raw)[sv];
        else       tg = ((const int*)alignment_raw)[sv];
        g_tgt[b * S_DIM + tid] = tg;
        const float a = attn[sidx];
        g_addval[b * S_DIM + tid] = a * copy;
        av = a;
        a0 = (tg == PAD_IDX) ? a : 0.f;
    }
    red[tid] = av; __syncthreads();
    for (int st = 128; st > 0; st >>= 1) {
        if (tid < st) red[tid] += red[tid + st];
        __syncthreads();
    }
    const float sumattn = red[0];
    __syncthreads();
    red[tid] = a0; __syncthreads();
    for (int st = 128; st > 0; st >>= 1) {
        if (tid < st) red[tid] += red[tid + st];
        __syncthreads();
    }
    const float scat0 = red[0];

    if (tid == 0) {
        const float l0 = g_logits[(size_t)b * V_DIM + PAD_IDX];
        const float prepad = (1.f - copy) * __expf(l0) / Z + copy * scat0;
        const float norm = (1.f - copy) + copy * sumattn - prepad + EPS_F;
        g_stats[b] = make_float4(0.f, 1.f / Z, copy, 1.f / norm);
    }
}

// ---------------- K3: streaming log-prob ----------------
#define K3_SPLIT 8
__global__ void __launch_bounds__(256)
final_stream_kernel(float* __restrict__ out)
{
    const int b = blockIdx.x;
    const float4 st = g_stats[b];
    const float invZ = st.y, copy = st.z, invnorm = st.w;
    const float k = (1.f - copy) * invZ * invnorm;
    const float4* in4 = (const float4*)(g_logits + (size_t)b * V_DIM);
    float4* out4 = (float4*)(out + (size_t)b * V_DIM);
    const int NV4 = V_DIM / 4;                 // 12500
    const int per = (NV4 + K3_SPLIT - 1) / K3_SPLIT;
    const int beg = blockIdx.y * per;
    const int end = (beg + per < NV4) ? beg + per : NV4;
    for (int i = beg + threadIdx.x; i < end; i += 256) {
        float4 v = in4[i];
        if (i == 1) v.x = 1e-10f;              // COPY (index 4)
        float4 r;
        r.x = __logf(k * __expf(v.x) + EPS_F);
        r.y = __logf(k * __expf(v.y) + EPS_F);
        r.z = __logf(k * __expf(v.z) + EPS_F);
        r.w = __logf(k * __expf(v.w) + EPS_F);
        if (i == 0) r.x = __logf(EPS_F * invnorm + EPS_F);   // PAD
        out4[i] = r;
    }
}

// ---------------- K4: scatter fixup (<=128 positions/row, dup-aggregating) --
__global__ void __launch_bounds__(128)
fixup_kernel(float* __restrict__ out)
{
    __shared__ int   stg[S_DIM];
    __shared__ float sad[S_DIM];
    const int b = blockIdx.x, t = threadIdx.x;
    stg[t] = g_tgt[b * S_DIM + t];
    sad[t] = g_addval[b * S_DIM + t];
    __syncthreads();
    const int tg = stg[t];
    if (tg == PAD_IDX) return;
    float tot = 0.f; bool first = true;
    for (int j = 0; j < S_DIM; ++j) {
        if (stg[j] == tg) { tot += sad[j]; if (j < t) first = false; }
    }
    if (!first) return;
    const float4 st = g_stats[b];
    const float l = (tg == COPY_IDX) ? 1e-10f : g_logits[(size_t)b * V_DIM + tg];
    const float p = (1.f - st.z) * st.y * __expf(l) + tot;
    out[(size_t)b * V_DIM + tg] = __logf(p * st.w + EPS_F);
}

// ---------------- launch ----------------
extern "C" void kernel_launch(void* const* d_in, const int* in_sizes, int n_in,
                              void* d_out, int out_size)
{
    const float* hidden    = (const float*)d_in[0];
    const void*  src       = d_in[1];
    const float* attn      = (const float*)d_in[2];
    const float* W         = (const float*)d_in[3];
    const float* bias      = (const float*)d_in[4];
    const void*  alignment = d_in[5];
    float*       out       = (float*)d_out;

    cudaFuncSetAttribute(gemm_kernel, cudaFuncAttributeMaxDynamicSharedMemorySize, SMEM_BYTES);

    dim3 g1(B_DIM / TM, NBLKS);                  // (8, 196) — M fastest for W L2 reuse
    gemm_kernel<<<g1, 256, SMEM_BYTES>>>(hidden, W, bias);

    stats_kernel<<<B_DIM, 256>>>(attn, src, alignment);

    dim3 g3(B_DIM, K3_SPLIT);
    final_stream_kernel<<<g3, 256>>>(out);

    fixup_kernel<<<B_DIM, S_DIM>>>(out);
}

// round 6
// speedup vs baseline: 2.0279x; 1.4781x over previous
#include <cuda_runtime.h>
#include <cuda_fp16.h>
#include <cstdint>

#define B_DIM   1024
#define S_DIM   128
#define H_DIM   1024
#define V_DIM   50000
#define COPY_IDX 4
#define PAD_IDX  0
#define EPS_F    1e-10f

// GEMM tiling: CTA 128(M) x 256(N) x 32(K), 8 warps of 64x64, fp16 m16n8k16
#define TM 128
#define TN 256
#define NBLKS ((V_DIM + TN - 1) / TN)   // 196
#define PARTS (NBLKS * 4)               // 784 partial sums per row
#define KITERS (H_DIM / 32)             // 32
#define NSTAGE 4

// smem layout (bytes). half rows padded to 40 halves (80B) for conflict-free ldmatrix.
#define SM_BIAS_B 0
#define SM_A_B    1024
#define A_STAGE_B (128 * 80)            // 10240
#define SM_B_B    (1024 + 4 * A_STAGE_B) // 41984
#define B_STAGE_B (256 * 80)            // 20480
#define SMEM_BYTES (SM_B_B + 4 * B_STAGE_B)  // 123904

// ---------------- scratch ----------------
__device__ float   g_logits[(size_t)B_DIM * V_DIM];    // 204.8 MB
__device__ __half2 g_Wh[(size_t)V_DIM * H_DIM / 2];    // 102.4 MB
__device__ __half2 g_hh[(size_t)B_DIM * H_DIM / 2];    // 2 MB
__device__ float   g_partial[(size_t)B_DIM * PARTS];   // 3.2 MB
__device__ float4  g_stats[B_DIM];                     // {0, 1/Z, copy, 1/norm}
__device__ int     g_tgt[B_DIM * S_DIM];
__device__ float   g_addval[B_DIM * S_DIM];

// ---------------- helpers ----------------
__device__ __forceinline__ uint32_t smem_u32(const void* p) {
    uint32_t a;
    asm("{ .reg .u64 t; cvta.to.shared.u64 t, %1; cvt.u32.u64 %0, t; }" : "=r"(a) : "l"(p));
    return a;
}
__device__ __forceinline__ void cp16(uint32_t dst, const void* src, int n) {
    asm volatile("cp.async.cg.shared.global [%0], [%1], 16, %2;\n" :: "r"(dst), "l"(src), "r"(n));
}
__device__ __forceinline__ void mma_f16(float* d, const uint32_t* a, const uint32_t* b) {
    asm volatile(
        "mma.sync.aligned.m16n8k16.row.col.f32.f16.f16.f32 "
        "{%0,%1,%2,%3},{%4,%5,%6,%7},{%8,%9},{%0,%1,%2,%3};\n"
        : "+f"(d[0]), "+f"(d[1]), "+f"(d[2]), "+f"(d[3])
        : "r"(a[0]), "r"(a[1]), "r"(a[2]), "r"(a[3]), "r"(b[0]), "r"(b[1]));
}
__device__ __forceinline__ void ldsm_x4(uint32_t* d, uint32_t a) {
    asm volatile("ldmatrix.sync.aligned.m8n8.x4.shared.b16 {%0,%1,%2,%3}, [%4];"
        : "=r"(d[0]), "=r"(d[1]), "=r"(d[2]), "=r"(d[3]) : "r"(a));
}
__device__ __forceinline__ void ldsm_x2(uint32_t* d, uint32_t a) {
    asm volatile("ldmatrix.sync.aligned.m8n8.x2.shared.b16 {%0,%1}, [%2];"
        : "=r"(d[0]), "=r"(d[1]) : "r"(a));
}
// int64-vs-int32 sniffing: int64 values < 2^31 have all odd 32-bit words zero.
__device__ __forceinline__ bool detect_i64(const int* p) {
    bool z = true;
#pragma unroll
    for (int i = 1; i < 32; i += 2) z = z && (p[i] == 0);
    return z;
}

// ---------------- K0: fp32 -> fp16 conversion ----------------
__global__ void __launch_bounds__(256)
convert_kernel(const float* __restrict__ W, const float* __restrict__ hidden)
{
    const size_t nW4 = (size_t)V_DIM * H_DIM / 4;   // 12.8M float4
    const size_t nH4 = (size_t)B_DIM * H_DIM / 4;
    const size_t stride = (size_t)gridDim.x * blockDim.x;
    const float4* W4 = (const float4*)W;
    const float4* H4 = (const float4*)hidden;
    for (size_t i = blockIdx.x * blockDim.x + threadIdx.x; i < nW4; i += stride) {
        const float4 v = W4[i];
        g_Wh[2 * i]     = __floats2half2_rn(v.x, v.y);
        g_Wh[2 * i + 1] = __floats2half2_rn(v.z, v.w);
    }
    for (size_t i = blockIdx.x * blockDim.x + threadIdx.x; i < nH4; i += stride) {
        const float4 v = H4[i];
        g_hh[2 * i]     = __floats2half2_rn(v.x, v.y);
        g_hh[2 * i + 1] = __floats2half2_rn(v.z, v.w);
    }
}

// ---------------- K1: fp16 mma GEMM + fused exp row-partials ----------------
__device__ __forceinline__ void load_stage(uint32_t a_u32, uint32_t b_u32,
                                           int mBlk, int nBlk, int k0, int tid)
{
    const __half* Ah = (const __half*)g_hh;
    const __half* Bh = (const __half*)g_Wh;
#pragma unroll
    for (int j = 0; j < 6; ++j) {
        const int t = tid + j * 256;
        if (t < 512) {                       // A: 128 rows x 4 chunks of 8 halves
            const int row = t >> 2, q = t & 3;
            const __half* src = Ah + (size_t)(mBlk + row) * H_DIM + k0 + q * 8;
            cp16(a_u32 + row * 80 + q * 16, src, 16);
        } else {                             // B: 256 rows x 4 chunks
            const int t2 = t - 512;
            const int row = t2 >> 2, q = t2 & 3;
            const int gn = nBlk + row;
            const int ok = (gn < V_DIM) ? 16 : 0;
            const __half* src = Bh + (size_t)(ok ? gn : 0) * H_DIM + k0 + q * 8;
            cp16(b_u32 + row * 80 + q * 16, src, ok);
        }
    }
}

__global__ void __launch_bounds__(256, 1)
gemm_kernel(const float* __restrict__ bias)
{
    extern __shared__ float smf[];
    const uint32_t sb = smem_u32(smf);

    const int tid   = threadIdx.x;
    const int lane  = tid & 31;
    const int wid   = tid >> 5;
    const int warpM = wid & 1;       // 0..1
    const int warpN = wid >> 1;      // 0..3
    const int r     = lane >> 2;     // 0..7
    const int cq    = lane & 3;      // 0..3

    const int mBlk = blockIdx.x * TM;
    const int nBlk = blockIdx.y * TN;

    // bias preload
    {
        const int c = nBlk + tid;
        smf[tid] = (c < V_DIM) ? bias[c] : 0.f;
    }

    // ldmatrix per-lane base addresses (bytes)
    // A x4: row = warpM*64 + mt*16 + (lane&15); halfcol = sl*16 + (lane>>4)*8
    const uint32_t aBase = sb + SM_A_B +
        (uint32_t)(warpM * 64 + (lane & 15)) * 80 + (uint32_t)(lane >> 4) * 16;
    // B x2: row = warpN*64 + nt*8 + (lane&7); halfcol = sl*16 + ((lane>>3)&1)*8
    const uint32_t bBase = sb + SM_B_B +
        (uint32_t)(warpN * 64 + (lane & 7)) * 80 + (uint32_t)((lane >> 3) & 1) * 16;

    float acc[4][8][4];
#pragma unroll
    for (int i = 0; i < 4; ++i)
#pragma unroll
        for (int j = 0; j < 8; ++j)
#pragma unroll
            for (int k = 0; k < 4; ++k) acc[i][j][k] = 0.f;

    // prologue: 3 stages
#pragma unroll
    for (int s = 0; s < NSTAGE - 1; ++s) {
        load_stage(sb + SM_A_B + s * A_STAGE_B, sb + SM_B_B + s * B_STAGE_B,
                   mBlk, nBlk, s * 32, tid);
        asm volatile("cp.async.commit_group;");
    }

    for (int ks = 0; ks < KITERS; ++ks) {
        asm volatile("cp.async.wait_group 2;");
        __syncthreads();

        const uint32_t aStage = aBase + (uint32_t)((ks & 3) * A_STAGE_B);
        const uint32_t bStage = bBase + (uint32_t)((ks & 3) * B_STAGE_B);

#pragma unroll
        for (int sl = 0; sl < 2; ++sl) {
            uint32_t afr[4][4];
            uint32_t bfr[8][2];
#pragma unroll
            for (int mt = 0; mt < 4; ++mt)
                ldsm_x4(afr[mt], aStage + (uint32_t)(mt * 16 * 80 + sl * 32));
#pragma unroll
            for (int nt = 0; nt < 8; ++nt)
                ldsm_x2(bfr[nt], bStage + (uint32_t)(nt * 8 * 80 + sl * 32));
#pragma unroll
            for (int mt = 0; mt < 4; ++mt)
#pragma unroll
                for (int nt = 0; nt < 8; ++nt)
                    mma_f16(acc[mt][nt], afr[mt], bfr[nt]);
        }

        const int tl = ks + NSTAGE - 1;
        if (tl < KITERS) {
            load_stage(sb + SM_A_B + (tl & 3) * A_STAGE_B,
                       sb + SM_B_B + (tl & 3) * B_STAGE_B,
                       mBlk, nBlk, tl * 32, tid);
        }
        asm volatile("cp.async.commit_group;");
    }

    // epilogue: bias add, store logits, per-row exp partial sums
    const float* bias_s = smf;
#pragma unroll
    for (int mt = 0; mt < 4; ++mt) {
        const int row0 = mBlk + warpM * 64 + mt * 16 + r;
        float rs0 = 0.f, rs1 = 0.f;
#pragma unroll
        for (int nt = 0; nt < 8; ++nt) {
            const int lc = warpN * 64 + nt * 8 + 2 * cq;
            const int gc = nBlk + lc;
            const float bv0 = bias_s[lc], bv1 = bias_s[lc + 1];
            const float v0 = acc[mt][nt][0] + bv0;
            const float v1 = acc[mt][nt][1] + bv1;
            const float v2 = acc[mt][nt][2] + bv0;
            const float v3 = acc[mt][nt][3] + bv1;
            if (gc < V_DIM) {   // V even, gc even => gc+1 < V too
                *(float2*)&g_logits[(size_t)row0 * V_DIM + gc]       = make_float2(v0, v1);
                *(float2*)&g_logits[(size_t)(row0 + 8) * V_DIM + gc] = make_float2(v2, v3);
                rs0 += __expf(v0) + __expf(v1);
                rs1 += __expf(v2) + __expf(v3);
            }
        }
        rs0 += __shfl_xor_sync(0xFFFFFFFF, rs0, 1);
        rs0 += __shfl_xor_sync(0xFFFFFFFF, rs0, 2);
        rs1 += __shfl_xor_sync(0xFFFFFFFF, rs1, 1);
        rs1 += __shfl_xor_sync(0xFFFFFFFF, rs1, 2);
        if (cq == 0) {
            const int pidx = blockIdx.y * 4 + warpN;
            g_partial[(size_t)row0 * PARTS + pidx]       = rs0;
            g_partial[(size_t)(row0 + 8) * PARTS + pidx] = rs1;
        }
    }
}

// ---------------- K2: stats (partials reduce + gather) ----------------
__global__ void __launch_bounds__(256)
stats_kernel(const float* __restrict__ attn,
             const void* __restrict__ src_raw,
             const void* __restrict__ alignment_raw)
{
    __shared__ float red[256];
    const int b   = blockIdx.x;
    const int tid = threadIdx.x;

    float s = 0.f;
    for (int i = tid; i < PARTS; i += 256) s += g_partial[(size_t)b * PARTS + i];
    red[tid] = s; __syncthreads();
    for (int st = 128; st > 0; st >>= 1) {
        if (tid < st) red[tid] += red[tid + st];
        __syncthreads();
    }
    const float Sraw = red[0];
    __syncthreads();

    const float l4 = g_logits[(size_t)b * V_DIM + COPY_IDX];
    const float Z  = Sraw - __expf(l4) + 1.0f;           // exp(1e-10) == 1.0f
    const float copy = 1.f / (1.f + __expf(-l4));

    const bool src64 = detect_i64((const int*)src_raw);
    const bool aln64 = detect_i64((const int*)alignment_raw);

    float av = 0.f, a0 = 0.f;
    if (tid < S_DIM) {
        const size_t sidx = (size_t)b * S_DIM + tid;
        long long sv;
        if (src64) sv = ((const long long*)src_raw)[sidx];
        else       sv = (long long)((const int*)src_raw)[sidx];
        int tg;
        if (aln64) tg = (int)((const long long*)alignment_raw)[sv];
        else       tg = ((const int*)alignment_raw)[sv];
        g_tgt[b * S_DIM + tid] = tg;
        const float a = attn[sidx];
        g_addval[b * S_DIM + tid] = a * copy;
        av = a;
        a0 = (tg == PAD_IDX) ? a : 0.f;
    }
    red[tid] = av; __syncthreads();
    for (int st = 128; st > 0; st >>= 1) {
        if (tid < st) red[tid] += red[tid + st];
        __syncthreads();
    }
    const float sumattn = red[0];
    __syncthreads();
    red[tid] = a0; __syncthreads();
    for (int st = 128; st > 0; st >>= 1) {
        if (tid < st) red[tid] += red[tid + st];
        __syncthreads();
    }
    const float scat0 = red[0];

    if (tid == 0) {
        const float l0 = g_logits[(size_t)b * V_DIM + PAD_IDX];
        const float prepad = (1.f - copy) * __expf(l0) / Z + copy * scat0;
        const float norm = (1.f - copy) + copy * sumattn - prepad + EPS_F;
        g_stats[b] = make_float4(0.f, 1.f / Z, copy, 1.f / norm);
    }
}

// ---------------- K3: streaming log-prob ----------------
#define K3_SPLIT 8
__global__ void __launch_bounds__(256)
final_stream_kernel(float* __restrict__ out)
{
    const int b = blockIdx.x;
    const float4 st = g_stats[b];
    const float invZ = st.y, copy = st.z, invnorm = st.w;
    const float k = (1.f - copy) * invZ * invnorm;
    const float4* in4 = (const float4*)(g_logits + (size_t)b * V_DIM);
    float4* out4 = (float4*)(out + (size_t)b * V_DIM);
    const int NV4 = V_DIM / 4;                 // 12500
    const int per = (NV4 + K3_SPLIT - 1) / K3_SPLIT;
    const int beg = blockIdx.y * per;
    const int end = (beg + per < NV4) ? beg + per : NV4;
    for (int i = beg + threadIdx.x; i < end; i += 256) {
        float4 v = in4[i];
        if (i == 1) v.x = 1e-10f;              // COPY (index 4)
        float4 r;
        r.x = __logf(k * __expf(v.x) + EPS_F);
        r.y = __logf(k * __expf(v.y) + EPS_F);
        r.z = __logf(k * __expf(v.z) + EPS_F);
        r.w = __logf(k * __expf(v.w) + EPS_F);
        if (i == 0) r.x = __logf(EPS_F * invnorm + EPS_F);   // PAD
        out4[i] = r;
    }
}

// ---------------- K4: scatter fixup (<=128 positions/row, dup-aggregating) --
__global__ void __launch_bounds__(128)
fixup_kernel(float* __restrict__ out)
{
    __shared__ int   stg[S_DIM];
    __shared__ float sad[S_DIM];
    const int b = blockIdx.x, t = threadIdx.x;
    stg[t] = g_tgt[b * S_DIM + t];
    sad[t] = g_addval[b * S_DIM + t];
    __syncthreads();
    const int tg = stg[t];
    if (tg == PAD_IDX) return;
    float tot = 0.f; bool first = true;
    for (int j = 0; j < S_DIM; ++j) {
        if (stg[j] == tg) { tot += sad[j]; if (j < t) first = false; }
    }
    if (!first) return;
    const float4 st = g_stats[b];
    const float l = (tg == COPY_IDX) ? 1e-10f : g_logits[(size_t)b * V_DIM + tg];
    const float p = (1.f - st.z) * st.y * __expf(l) + tot;
    out[(size_t)b * V_DIM + tg] = __logf(p * st.w + EPS_F);
}

// ---------------- launch ----------------
extern "C" void kernel_launch(void* const* d_in, const int* in_sizes, int n_in,
                              void* d_out, int out_size)
{
    const float* hidden    = (const float*)d_in[0];
    const void*  src       = d_in[1];
    const float* attn      = (const float*)d_in[2];
    const float* W         = (const float*)d_in[3];
    const float* bias      = (const float*)d_in[4];
    const void*  alignment = d_in[5];
    float*       out       = (float*)d_out;

    cudaFuncSetAttribute(gemm_kernel, cudaFuncAttributeMaxDynamicSharedMemorySize, SMEM_BYTES);

    convert_kernel<<<1184, 256>>>(W, hidden);

    dim3 g1(B_DIM / TM, NBLKS);                  // (8, 196) — M fastest for W L2 reuse
    gemm_kernel<<<g1, 256, SMEM_BYTES>>>(bias);

    stats_kernel<<<B_DIM, 256>>>(attn, src, alignment);

    dim3 g3(B_DIM, K3_SPLIT);
    final_stream_kernel<<<g3, 256>>>(out);

    fixup_kernel<<<B_DIM, S_DIM>>>(out);
}

// round 7
// speedup vs baseline: 2.1103x; 1.0407x over previous
#include <cuda_runtime.h>
#include <cuda_fp16.h>
#include <cstdint>

#define B_DIM   1024
#define S_DIM   128
#define H_DIM   1024
#define V_DIM   50000
#define COPY_IDX 4
#define PAD_IDX  0
#define EPS_F    1e-10f

// GEMM tiling: CTA 128(M) x 256(N) x 32(K), 8 warps of 64x64, fp16 m16n8k16, f16 acc
#define TM 128
#define TN 256
#define NBLKS ((V_DIM + TN - 1) / TN)   // 196
#define PARTS (NBLKS * 4)               // 784 partial sums per row
#define KITERS (H_DIM / 32)             // 32
#define NSTAGE 4

// smem layout (bytes). half rows padded to 40 halves (80B) for conflict-free ldmatrix.
#define SM_BIAS_B 0
#define SM_A_B    1024
#define A_STAGE_B (128 * 80)            // 10240
#define SM_B_B    (1024 + 4 * A_STAGE_B) // 41984
#define B_STAGE_B (256 * 80)            // 20480
#define SMEM_BYTES (SM_B_B + 4 * B_STAGE_B)  // 123904

// ---------------- scratch ----------------
__device__ __half  g_logits[(size_t)B_DIM * V_DIM];    // 102.4 MB (fp16 logits)
__device__ __half2 g_Wh[(size_t)V_DIM * H_DIM / 2];    // 102.4 MB
__device__ __half2 g_hh[(size_t)B_DIM * H_DIM / 2];    // 2 MB
__device__ float   g_partial[(size_t)B_DIM * PARTS];   // 3.2 MB
__device__ float4  g_stats[B_DIM];                     // {0, 1/Z, copy, 1/norm}
__device__ int     g_tgt[B_DIM * S_DIM];
__device__ float   g_addval[B_DIM * S_DIM];

// ---------------- helpers ----------------
__device__ __forceinline__ uint32_t smem_u32(const void* p) {
    uint32_t a;
    asm("{ .reg .u64 t; cvta.to.shared.u64 t, %1; cvt.u32.u64 %0, t; }" : "=r"(a) : "l"(p));
    return a;
}
__device__ __forceinline__ void cp16(uint32_t dst, const void* src, int n) {
    asm volatile("cp.async.cg.shared.global [%0], [%1], 16, %2;\n" :: "r"(dst), "l"(src), "r"(n));
}
// fp16-accumulator mma: d/c are 2 x b32 (half2 pairs). Layout: d0 = {c0,c1}@row r,
// d1 = {c0,c1}@row r+8 (same element positions as the f32 variant, packed).
__device__ __forceinline__ void mma_f16acc(uint32_t* d, const uint32_t* a, const uint32_t* b) {
    asm volatile(
        "mma.sync.aligned.m16n8k16.row.col.f16.f16.f16.f16 "
        "{%0,%1},{%2,%3,%4,%5},{%6,%7},{%0,%1};\n"
        : "+r"(d[0]), "+r"(d[1])
        : "r"(a[0]), "r"(a[1]), "r"(a[2]), "r"(a[3]), "r"(b[0]), "r"(b[1]));
}
__device__ __forceinline__ void ldsm_x4(uint32_t* d, uint32_t a) {
    asm volatile("ldmatrix.sync.aligned.m8n8.x4.shared.b16 {%0,%1,%2,%3}, [%4];"
        : "=r"(d[0]), "=r"(d[1]), "=r"(d[2]), "=r"(d[3]) : "r"(a));
}
__device__ __forceinline__ void ldsm_x2(uint32_t* d, uint32_t a) {
    asm volatile("ldmatrix.sync.aligned.m8n8.x2.shared.b16 {%0,%1}, [%2];"
        : "=r"(d[0]), "=r"(d[1]) : "r"(a));
}
// int64-vs-int32 sniffing: int64 values < 2^31 have all odd 32-bit words zero.
__device__ __forceinline__ bool detect_i64(const int* p) {
    bool z = true;
#pragma unroll
    for (int i = 1; i < 32; i += 2) z = z && (p[i] == 0);
    return z;
}

// ---------------- K0: fp32 -> fp16 conversion ----------------
__global__ void __launch_bounds__(256)
convert_kernel(const float* __restrict__ W, const float* __restrict__ hidden)
{
    const size_t nW4 = (size_t)V_DIM * H_DIM / 4;   // 12.8M float4
    const size_t nH4 = (size_t)B_DIM * H_DIM / 4;
    const size_t stride = (size_t)gridDim.x * blockDim.x;
    const float4* W4 = (const float4*)W;
    const float4* H4 = (const float4*)hidden;
    for (size_t i = blockIdx.x * blockDim.x + threadIdx.x; i < nW4; i += stride) {
        const float4 v = W4[i];
        g_Wh[2 * i]     = __floats2half2_rn(v.x, v.y);
        g_Wh[2 * i + 1] = __floats2half2_rn(v.z, v.w);
    }
    for (size_t i = blockIdx.x * blockDim.x + threadIdx.x; i < nH4; i += stride) {
        const float4 v = H4[i];
        g_hh[2 * i]     = __floats2half2_rn(v.x, v.y);
        g_hh[2 * i + 1] = __floats2half2_rn(v.z, v.w);
    }
}

// ---------------- K1: fp16 mma GEMM + fused exp row-partials ----------------
__device__ __forceinline__ void load_stage(uint32_t a_u32, uint32_t b_u32,
                                           int mBlk, int nBlk, int k0, int tid)
{
    const __half* Ah = (const __half*)g_hh;
    const __half* Bh = (const __half*)g_Wh;
#pragma unroll
    for (int j = 0; j < 6; ++j) {
        const int t = tid + j * 256;
        if (t < 512) {                       // A: 128 rows x 4 chunks of 8 halves
            const int row = t >> 2, q = t & 3;
            const __half* src = Ah + (size_t)(mBlk + row) * H_DIM + k0 + q * 8;
            cp16(a_u32 + row * 80 + q * 16, src, 16);
        } else {                             // B: 256 rows x 4 chunks
            const int t2 = t - 512;
            const int row = t2 >> 2, q = t2 & 3;
            const int gn = nBlk + row;
            const int ok = (gn < V_DIM) ? 16 : 0;
            const __half* src = Bh + (size_t)(ok ? gn : 0) * H_DIM + k0 + q * 8;
            cp16(b_u32 + row * 80 + q * 16, src, ok);
        }
    }
}

__global__ void __launch_bounds__(256, 1)
gemm_kernel(const float* __restrict__ bias)
{
    extern __shared__ float smf[];
    const uint32_t sb = smem_u32(smf);

    const int tid   = threadIdx.x;
    const int lane  = tid & 31;
    const int wid   = tid >> 5;
    const int warpM = wid & 1;       // 0..1
    const int warpN = wid >> 1;      // 0..3
    const int r     = lane >> 2;     // 0..7
    const int cq    = lane & 3;      // 0..3

    const int mBlk = blockIdx.x * TM;
    const int nBlk = blockIdx.y * TN;

    // bias preload
    {
        const int c = nBlk + tid;
        smf[tid] = (c < V_DIM) ? bias[c] : 0.f;
    }

    // ldmatrix per-lane base addresses (bytes)
    const uint32_t aBase = sb + SM_A_B +
        (uint32_t)(warpM * 64 + (lane & 15)) * 80 + (uint32_t)(lane >> 4) * 16;
    const uint32_t bBase = sb + SM_B_B +
        (uint32_t)(warpN * 64 + (lane & 7)) * 80 + (uint32_t)((lane >> 3) & 1) * 16;

    uint32_t acc[4][8][2];   // half2 accumulators
#pragma unroll
    for (int i = 0; i < 4; ++i)
#pragma unroll
        for (int j = 0; j < 8; ++j) { acc[i][j][0] = 0u; acc[i][j][1] = 0u; }

    // prologue: 3 stages
#pragma unroll
    for (int s = 0; s < NSTAGE - 1; ++s) {
        load_stage(sb + SM_A_B + s * A_STAGE_B, sb + SM_B_B + s * B_STAGE_B,
                   mBlk, nBlk, s * 32, tid);
        asm volatile("cp.async.commit_group;");
    }

    for (int ks = 0; ks < KITERS; ++ks) {
        asm volatile("cp.async.wait_group 2;");
        __syncthreads();

        const uint32_t aStage = aBase + (uint32_t)((ks & 3) * A_STAGE_B);
        const uint32_t bStage = bBase + (uint32_t)((ks & 3) * B_STAGE_B);

#pragma unroll
        for (int sl = 0; sl < 2; ++sl) {
            uint32_t afr[4][4];
            uint32_t bfr[8][2];
#pragma unroll
            for (int mt = 0; mt < 4; ++mt)
                ldsm_x4(afr[mt], aStage + (uint32_t)(mt * 16 * 80 + sl * 32));
#pragma unroll
            for (int nt = 0; nt < 8; ++nt)
                ldsm_x2(bfr[nt], bStage + (uint32_t)(nt * 8 * 80 + sl * 32));
#pragma unroll
            for (int mt = 0; mt < 4; ++mt)
#pragma unroll
                for (int nt = 0; nt < 8; ++nt)
                    mma_f16acc(acc[mt][nt], afr[mt], bfr[nt]);
        }

        const int tl = ks + NSTAGE - 1;
        if (tl < KITERS) {
            load_stage(sb + SM_A_B + (tl & 3) * A_STAGE_B,
                       sb + SM_B_B + (tl & 3) * B_STAGE_B,
                       mBlk, nBlk, tl * 32, tid);
        }
        asm volatile("cp.async.commit_group;");
    }

    // epilogue: bias add (fp32), round-to-half store, exp partials from the
    // STORED half values (exact consistency with K3's reads).
    const float* bias_s = smf;
#pragma unroll
    for (int mt = 0; mt < 4; ++mt) {
        const int row0 = mBlk + warpM * 64 + mt * 16 + r;
        float rs0 = 0.f, rs1 = 0.f;
#pragma unroll
        for (int nt = 0; nt < 8; ++nt) {
            const int lc = warpN * 64 + nt * 8 + 2 * cq;
            const int gc = nBlk + lc;
            const float bv0 = bias_s[lc], bv1 = bias_s[lc + 1];
            const __half2 a01 = *(__half2*)&acc[mt][nt][0];
            const __half2 a23 = *(__half2*)&acc[mt][nt][1];
            const float v0 = __low2float(a01) + bv0;
            const float v1 = __high2float(a01) + bv1;
            const float v2 = __low2float(a23) + bv0;
            const float v3 = __high2float(a23) + bv1;
            if (gc < V_DIM) {   // V even, gc even => gc+1 < V too
                const __half2 s01 = __floats2half2_rn(v0, v1);
                const __half2 s23 = __floats2half2_rn(v2, v3);
                *(__half2*)&g_logits[(size_t)row0 * V_DIM + gc]       = s01;
                *(__half2*)&g_logits[(size_t)(row0 + 8) * V_DIM + gc] = s23;
                const float2 e01 = __half22float2(s01);
                const float2 e23 = __half22float2(s23);
                rs0 += __expf(e01.x) + __expf(e01.y);
                rs1 += __expf(e23.x) + __expf(e23.y);
            }
        }
        rs0 += __shfl_xor_sync(0xFFFFFFFF, rs0, 1);
        rs0 += __shfl_xor_sync(0xFFFFFFFF, rs0, 2);
        rs1 += __shfl_xor_sync(0xFFFFFFFF, rs1, 1);
        rs1 += __shfl_xor_sync(0xFFFFFFFF, rs1, 2);
        if (cq == 0) {
            const int pidx = blockIdx.y * 4 + warpN;
            g_partial[(size_t)row0 * PARTS + pidx]       = rs0;
            g_partial[(size_t)(row0 + 8) * PARTS + pidx] = rs1;
        }
    }
}

// ---------------- K2: stats (partials reduce + gather) ----------------
__global__ void __launch_bounds__(256)
stats_kernel(const float* __restrict__ attn,
             const void* __restrict__ src_raw,
             const void* __restrict__ alignment_raw)
{
    __shared__ float red[256];
    const int b   = blockIdx.x;
    const int tid = threadIdx.x;

    float s = 0.f;
    for (int i = tid; i < PARTS; i += 256) s += g_partial[(size_t)b * PARTS + i];
    red[tid] = s; __syncthreads();
    for (int st = 128; st > 0; st >>= 1) {
        if (tid < st) red[tid] += red[tid + st];
        __syncthreads();
    }
    const float Sraw = red[0];
    __syncthreads();

    const float l4 = __half2float(g_logits[(size_t)b * V_DIM + COPY_IDX]);
    const float Z  = Sraw - __expf(l4) + 1.0f;           // exp(1e-10) == 1.0f
    const float copy = 1.f / (1.f + __expf(-l4));

    const bool src64 = detect_i64((const int*)src_raw);
    const bool aln64 = detect_i64((const int*)alignment_raw);

    float av = 0.f, a0 = 0.f;
    if (tid < S_DIM) {
        const size_t sidx = (size_t)b * S_DIM + tid;
        long long sv;
        if (src64) sv = ((const long long*)src_raw)[sidx];
        else       sv = (long long)((const int*)src_raw)[sidx];
        int tg;
        if (aln64) tg = (int)((const long long*)alignment_raw)[sv];
        else       tg = ((const int*)alignment_raw)[sv];
        g_tgt[b * S_DIM + tid] = tg;
        const float a = attn[sidx];
        g_addval[b * S_DIM + tid] = a * copy;
        av = a;
        a0 = (tg == PAD_IDX) ? a : 0.f;
    }
    red[tid] = av; __syncthreads();
    for (int st = 128; st > 0; st >>= 1) {
        if (tid < st) red[tid] += red[tid + st];
        __syncthreads();
    }
    const float sumattn = red[0];
    __syncthreads();
    red[tid] = a0; __syncthreads();
    for (int st = 128; st > 0; st >>= 1) {
        if (tid < st) red[tid] += red[tid + st];
        __syncthreads();
    }
    const float scat0 = red[0];

    if (tid == 0) {
        const float l0 = __half2float(g_logits[(size_t)b * V_DIM + PAD_IDX]);
        const float prepad = (1.f - copy) * __expf(l0) / Z + copy * scat0;
        const float norm = (1.f - copy) + copy * sumattn - prepad + EPS_F;
        g_stats[b] = make_float4(0.f, 1.f / Z, copy, 1.f / norm);
    }
}

// ---------------- K3: streaming log-prob (half in, float out) ----------------
#define K3_SPLIT 8
__global__ void __launch_bounds__(256)
final_stream_kernel(float* __restrict__ out)
{
    const int b = blockIdx.x;
    const float4 st = g_stats[b];
    const float invZ = st.y, copy = st.z, invnorm = st.w;
    const float k = (1.f - copy) * invZ * invnorm;
    const uint4* in8 = (const uint4*)(g_logits + (size_t)b * V_DIM);  // 8 halves each
    float4* out4 = (float4*)(out + (size_t)b * V_DIM);
    const int NV8 = V_DIM / 8;                 // 6250
    const int per = (NV8 + K3_SPLIT - 1) / K3_SPLIT;
    const int beg = blockIdx.y * per;
    const int end = (beg + per < NV8) ? beg + per : NV8;
    for (int i = beg + threadIdx.x; i < end; i += 256) {
        const uint4 u = in8[i];
        float2 p0 = __half22float2(*(const __half2*)&u.x);
        float2 p1 = __half22float2(*(const __half2*)&u.y);
        float2 p2 = __half22float2(*(const __half2*)&u.z);
        float2 p3 = __half22float2(*(const __half2*)&u.w);
        if (i == 0) p2.x = 1e-10f;             // COPY (element 4)
        float4 r0, r1;
        r0.x = __logf(k * __expf(p0.x) + EPS_F);
        r0.y = __logf(k * __expf(p0.y) + EPS_F);
        r0.z = __logf(k * __expf(p1.x) + EPS_F);
        r0.w = __logf(k * __expf(p1.y) + EPS_F);
        r1.x = __logf(k * __expf(p2.x) + EPS_F);
        r1.y = __logf(k * __expf(p2.y) + EPS_F);
        r1.z = __logf(k * __expf(p3.x) + EPS_F);
        r1.w = __logf(k * __expf(p3.y) + EPS_F);
        if (i == 0) r0.x = __logf(EPS_F * invnorm + EPS_F);   // PAD
        out4[2 * i]     = r0;
        out4[2 * i + 1] = r1;
    }
}

// ---------------- K4: scatter fixup (<=128 positions/row, dup-aggregating) --
__global__ void __launch_bounds__(128)
fixup_kernel(float* __restrict__ out)
{
    __shared__ int   stg[S_DIM];
    __shared__ float sad[S_DIM];
    const int b = blockIdx.x, t = threadIdx.x;
    stg[t] = g_tgt[b * S_DIM + t];
    sad[t] = g_addval[b * S_DIM + t];
    __syncthreads();
    const int tg = stg[t];
    if (tg == PAD_IDX) return;
    float tot = 0.f; bool first = true;
    for (int j = 0; j < S_DIM; ++j) {
        if (stg[j] == tg) { tot += sad[j]; if (j < t) first = false; }
    }
    if (!first) return;
    const float4 st = g_stats[b];
    const float l = (tg == COPY_IDX) ? 1e-10f
                                     : __half2float(g_logits[(size_t)b * V_DIM + tg]);
    const float p = (1.f - st.z) * st.y * __expf(l) + tot;
    out[(size_t)b * V_DIM + tg] = __logf(p * st.w + EPS_F);
}

// ---------------- launch ----------------
extern "C" void kernel_launch(void* const* d_in, const int* in_sizes, int n_in,
                              void* d_out, int out_size)
{
    const float* hidden    = (const float*)d_in[0];
    const void*  src       = d_in[1];
    const float* attn      = (const float*)d_in[2];
    const float* W         = (const float*)d_in[3];
    const float* bias      = (const float*)d_in[4];
    const void*  alignment = d_in[5];
    float*       out       = (float*)d_out;

    cudaFuncSetAttribute(gemm_kernel, cudaFuncAttributeMaxDynamicSharedMemorySize, SMEM_BYTES);

    convert_kernel<<<1184, 256>>>(W, hidden);

    dim3 g1(B_DIM / TM, NBLKS);                  // (8, 196) — M fastest for W L2 reuse
    gemm_kernel<<<g1, 256, SMEM_BYTES>>>(bias);

    stats_kernel<<<B_DIM, 256>>>(attn, src, alignment);

    dim3 g3(B_DIM, K3_SPLIT);
    final_stream_kernel<<<g3, 256>>>(out);

    fixup_kernel<<<B_DIM, S_DIM>>>(out);
}

// round 8
// speedup vs baseline: 2.5286x; 1.1982x over previous
#include <cuda_runtime.h>
#include <cuda_fp16.h>
#include <cstdint>

#define B_DIM   1024
#define S_DIM   128
#define H_DIM   1024
#define V_DIM   50000
#define COPY_IDX 4
#define PAD_IDX  0
#define EPS_F    1e-10f

// GEMM tiling: CTA 128(M) x 256(N) x 32(K), 8 warps of 64x64, fp16 m16n8k16, f16 acc
#define TM 128
#define TN 256
#define NBLKS ((V_DIM + TN - 1) / TN)   // 196
#define PARTS (NBLKS * 4)               // 784 partial sums per row
#define KITERS (H_DIM / 32)             // 32
#define NSTAGE 3                        // 3 stages -> 93KB smem -> 2 CTAs/SM

// smem layout (bytes). half rows padded to 40 halves (80B) for conflict-free ldmatrix.
#define SM_BIAS_B 0
#define SM_A_B    1024
#define A_STAGE_B (128 * 80)             // 10240
#define SM_B_B    (1024 + NSTAGE * A_STAGE_B)   // 31744
#define B_STAGE_B (256 * 80)             // 20480
#define SMEM_BYTES (SM_B_B + NSTAGE * B_STAGE_B)  // 93184

// ---------------- scratch ----------------
__device__ __half  g_logits[(size_t)B_DIM * V_DIM];    // 102.4 MB (fp16 logits)
__device__ __half2 g_Wh[(size_t)V_DIM * H_DIM / 2];    // 102.4 MB
__device__ __half2 g_hh[(size_t)B_DIM * H_DIM / 2];    // 2 MB
__device__ float   g_partial[(size_t)B_DIM * PARTS];   // 3.2 MB
__device__ float4  g_stats[B_DIM];                     // {0, 1/Z, copy, 1/norm}
__device__ int     g_tgt[B_DIM * S_DIM];
__device__ float   g_addval[B_DIM * S_DIM];

// ---------------- helpers ----------------
__device__ __forceinline__ uint32_t smem_u32(const void* p) {
    uint32_t a;
    asm("{ .reg .u64 t; cvta.to.shared.u64 t, %1; cvt.u32.u64 %0, t; }" : "=r"(a) : "l"(p));
    return a;
}
__device__ __forceinline__ void cp16(uint32_t dst, const void* src, int n) {
    asm volatile("cp.async.cg.shared.global [%0], [%1], 16, %2;\n" :: "r"(dst), "l"(src), "r"(n));
}
// fp16-accumulator mma
__device__ __forceinline__ void mma_f16acc(uint32_t* d, const uint32_t* a, const uint32_t* b) {
    asm volatile(
        "mma.sync.aligned.m16n8k16.row.col.f16.f16.f16.f16 "
        "{%0,%1},{%2,%3,%4,%5},{%6,%7},{%0,%1};\n"
        : "+r"(d[0]), "+r"(d[1])
        : "r"(a[0]), "r"(a[1]), "r"(a[2]), "r"(a[3]), "r"(b[0]), "r"(b[1]));
}
__device__ __forceinline__ void ldsm_x4(uint32_t* d, uint32_t a) {
    asm volatile("ldmatrix.sync.aligned.m8n8.x4.shared.b16 {%0,%1,%2,%3}, [%4];"
        : "=r"(d[0]), "=r"(d[1]), "=r"(d[2]), "=r"(d[3]) : "r"(a));
}
__device__ __forceinline__ void ldsm_x2(uint32_t* d, uint32_t a) {
    asm volatile("ldmatrix.sync.aligned.m8n8.x2.shared.b16 {%0,%1}, [%2];"
        : "=r"(d[0]), "=r"(d[1]) : "r"(a));
}
// int64-vs-int32 sniffing: int64 values < 2^31 have all odd 32-bit words zero.
__device__ __forceinline__ bool detect_i64(const int* p) {
    bool z = true;
#pragma unroll
    for (int i = 1; i < 32; i += 2) z = z && (p[i] == 0);
    return z;
}

// ---------------- K0: fp32 -> fp16 conversion ----------------
__global__ void __launch_bounds__(256)
convert_kernel(const float* __restrict__ W, const float* __restrict__ hidden)
{
    const size_t nW4 = (size_t)V_DIM * H_DIM / 4;
    const size_t nH4 = (size_t)B_DIM * H_DIM / 4;
    const size_t stride = (size_t)gridDim.x * blockDim.x;
    const float4* W4 = (const float4*)W;
    const float4* H4 = (const float4*)hidden;
    for (size_t i = blockIdx.x * blockDim.x + threadIdx.x; i < nW4; i += stride) {
        const float4 v = W4[i];
        g_Wh[2 * i]     = __floats2half2_rn(v.x, v.y);
        g_Wh[2 * i + 1] = __floats2half2_rn(v.z, v.w);
    }
    for (size_t i = blockIdx.x * blockDim.x + threadIdx.x; i < nH4; i += stride) {
        const float4 v = H4[i];
        g_hh[2 * i]     = __floats2half2_rn(v.x, v.y);
        g_hh[2 * i + 1] = __floats2half2_rn(v.z, v.w);
    }
}

// ---------------- K1: fp16 mma GEMM + fused exp row-partials ----------------
__device__ __forceinline__ void load_stage(uint32_t a_u32, uint32_t b_u32,
                                           int mBlk, int nBlk, int k0, int tid)
{
    const __half* Ah = (const __half*)g_hh;
    const __half* Bh = (const __half*)g_Wh;
#pragma unroll
    for (int j = 0; j < 6; ++j) {
        const int t = tid + j * 256;
        if (t < 512) {                       // A: 128 rows x 4 chunks of 8 halves
            const int row = t >> 2, q = t & 3;
            const __half* src = Ah + (size_t)(mBlk + row) * H_DIM + k0 + q * 8;
            cp16(a_u32 + row * 80 + q * 16, src, 16);
        } else {                             // B: 256 rows x 4 chunks
            const int t2 = t - 512;
            const int row = t2 >> 2, q = t2 & 3;
            const int gn = nBlk + row;
            const int ok = (gn < V_DIM) ? 16 : 0;
            const __half* src = Bh + (size_t)(ok ? gn : 0) * H_DIM + k0 + q * 8;
            cp16(b_u32 + row * 80 + q * 16, src, ok);
        }
    }
}

__global__ void __launch_bounds__(256, 2)
gemm_kernel(const float* __restrict__ bias)
{
    extern __shared__ float smf[];
    const uint32_t sb = smem_u32(smf);

    const int tid   = threadIdx.x;
    const int lane  = tid & 31;
    const int wid   = tid >> 5;
    const int warpM = wid & 1;       // 0..1
    const int warpN = wid >> 1;      // 0..3
    const int r     = lane >> 2;     // 0..7
    const int cq    = lane & 3;      // 0..3

    const int mBlk = blockIdx.x * TM;
    const int nBlk = blockIdx.y * TN;

    // bias preload
    {
        const int c = nBlk + tid;
        smf[tid] = (c < V_DIM) ? bias[c] : 0.f;
    }

    // ldmatrix per-lane base addresses (bytes)
    const uint32_t aBase = sb + SM_A_B +
        (uint32_t)(warpM * 64 + (lane & 15)) * 80 + (uint32_t)(lane >> 4) * 16;
    const uint32_t bBase = sb + SM_B_B +
        (uint32_t)(warpN * 64 + (lane & 7)) * 80 + (uint32_t)((lane >> 3) & 1) * 16;

    uint32_t acc[4][8][2];   // half2 accumulators
#pragma unroll
    for (int i = 0; i < 4; ++i)
#pragma unroll
        for (int j = 0; j < 8; ++j) { acc[i][j][0] = 0u; acc[i][j][1] = 0u; }

    // prologue: 2 stages
#pragma unroll
    for (int s = 0; s < NSTAGE - 1; ++s) {
        load_stage(sb + SM_A_B + s * A_STAGE_B, sb + SM_B_B + s * B_STAGE_B,
                   mBlk, nBlk, s * 32, tid);
        asm volatile("cp.async.commit_group;");
    }

    int sIdx = 0;   // stage slot of iteration ks
    for (int ks = 0; ks < KITERS; ++ks) {
        asm volatile("cp.async.wait_group 1;");
        __syncthreads();

        const uint32_t aStage = aBase + (uint32_t)(sIdx * A_STAGE_B);
        const uint32_t bStage = bBase + (uint32_t)(sIdx * B_STAGE_B);

#pragma unroll
        for (int sl = 0; sl < 2; ++sl) {
            uint32_t afr[4][4];
            uint32_t bfr[8][2];
#pragma unroll
            for (int mt = 0; mt < 4; ++mt)
                ldsm_x4(afr[mt], aStage + (uint32_t)(mt * 16 * 80 + sl * 32));
#pragma unroll
            for (int nt = 0; nt < 8; ++nt)
                ldsm_x2(bfr[nt], bStage + (uint32_t)(nt * 8 * 80 + sl * 32));
#pragma unroll
            for (int mt = 0; mt < 4; ++mt)
#pragma unroll
                for (int nt = 0; nt < 8; ++nt)
                    mma_f16acc(acc[mt][nt], afr[mt], bfr[nt]);
        }

        const int tl = ks + NSTAGE - 1;
        if (tl < KITERS) {
            // slot being refilled == slot (ks+2) % 3 == slot we just freed next iter
            int fillSlot = sIdx + (NSTAGE - 1);
            if (fillSlot >= NSTAGE) fillSlot -= NSTAGE;
            load_stage(sb + SM_A_B + fillSlot * A_STAGE_B,
                       sb + SM_B_B + fillSlot * B_STAGE_B,
                       mBlk, nBlk, tl * 32, tid);
        }
        asm volatile("cp.async.commit_group;");
        if (++sIdx == NSTAGE) sIdx = 0;
    }

    // epilogue: bias add (fp32), round-to-half store, exp partials from the
    // STORED half values (exact consistency with K3's reads).
    const float* bias_s = smf;
#pragma unroll
    for (int mt = 0; mt < 4; ++mt) {
        const int row0 = mBlk + warpM * 64 + mt * 16 + r;
        float rs0 = 0.f, rs1 = 0.f;
#pragma unroll
        for (int nt = 0; nt < 8; ++nt) {
            const int lc = warpN * 64 + nt * 8 + 2 * cq;
            const int gc = nBlk + lc;
            const float bv0 = bias_s[lc], bv1 = bias_s[lc + 1];
            const __half2 a01 = *(__half2*)&acc[mt][nt][0];
            const __half2 a23 = *(__half2*)&acc[mt][nt][1];
            const float v0 = __low2float(a01) + bv0;
            const float v1 = __high2float(a01) + bv1;
            const float v2 = __low2float(a23) + bv0;
            const float v3 = __high2float(a23) + bv1;
            if (gc < V_DIM) {   // V even, gc even => gc+1 < V too
                const __half2 s01 = __floats2half2_rn(v0, v1);
                const __half2 s23 = __floats2half2_rn(v2, v3);
                *(__half2*)&g_logits[(size_t)row0 * V_DIM + gc]       = s01;
                *(__half2*)&g_logits[(size_t)(row0 + 8) * V_DIM + gc] = s23;
                const float2 e01 = __half22float2(s01);
                const float2 e23 = __half22float2(s23);
                rs0 += __expf(e01.x) + __expf(e01.y);
                rs1 += __expf(e23.x) + __expf(e23.y);
            }
        }
        rs0 += __shfl_xor_sync(0xFFFFFFFF, rs0, 1);
        rs0 += __shfl_xor_sync(0xFFFFFFFF, rs0, 2);
        rs1 += __shfl_xor_sync(0xFFFFFFFF, rs1, 1);
        rs1 += __shfl_xor_sync(0xFFFFFFFF, rs1, 2);
        if (cq == 0) {
            const int pidx = blockIdx.y * 4 + warpN;
            g_partial[(size_t)row0 * PARTS + pidx]       = rs0;
            g_partial[(size_t)(row0 + 8) * PARTS + pidx] = rs1;
        }
    }
}

// ---------------- K2: stats (partials reduce + gather) ----------------
__global__ void __launch_bounds__(256)
stats_kernel(const float* __restrict__ attn,
             const void* __restrict__ src_raw,
             const void* __restrict__ alignment_raw)
{
    __shared__ float red[256];
    const int b   = blockIdx.x;
    const int tid = threadIdx.x;

    float s = 0.f;
    for (int i = tid; i < PARTS; i += 256) s += g_partial[(size_t)b * PARTS + i];
    red[tid] = s; __syncthreads();
    for (int st = 128; st > 0; st >>= 1) {
        if (tid < st) red[tid] += red[tid + st];
        __syncthreads();
    }
    const float Sraw = red[0];
    __syncthreads();

    const float l4 = __half2float(g_logits[(size_t)b * V_DIM + COPY_IDX]);
    const float Z  = Sraw - __expf(l4) + 1.0f;           // exp(1e-10) == 1.0f
    const float copy = 1.f / (1.f + __expf(-l4));

    const bool src64 = detect_i64((const int*)src_raw);
    const bool aln64 = detect_i64((const int*)alignment_raw);

    float av = 0.f, a0 = 0.f;
    if (tid < S_DIM) {
        const size_t sidx = (size_t)b * S_DIM + tid;
        long long sv;
        if (src64) sv = ((const long long*)src_raw)[sidx];
        else       sv = (long long)((const int*)src_raw)[sidx];
        int tg;
        if (aln64) tg = (int)((const long long*)alignment_raw)[sv];
        else       tg = ((const int*)alignment_raw)[sv];
        g_tgt[b * S_DIM + tid] = tg;
        const float a = attn[sidx];
        g_addval[b * S_DIM + tid] = a * copy;
        av = a;
        a0 = (tg == PAD_IDX) ? a : 0.f;
    }
    red[tid] = av; __syncthreads();
    for (int st = 128; st > 0; st >>= 1) {
        if (tid < st) red[tid] += red[tid + st];
        __syncthreads();
    }
    const float sumattn = red[0];
    __syncthreads();
    red[tid] = a0; __syncthreads();
    for (int st = 128; st > 0; st >>= 1) {
        if (tid < st) red[tid] += red[tid + st];
        __syncthreads();
    }
    const float scat0 = red[0];

    if (tid == 0) {
        const float l0 = __half2float(g_logits[(size_t)b * V_DIM + PAD_IDX]);
        const float prepad = (1.f - copy) * __expf(l0) / Z + copy * scat0;
        const float norm = (1.f - copy) + copy * sumattn - prepad + EPS_F;
        g_stats[b] = make_float4(0.f, 1.f / Z, copy, 1.f / norm);
    }
}

// ---------------- K3: streaming log-prob:  out = log(k) + logit ----------------
// k*e^x >= ~4e-7 >> eps=1e-10, so log(k e^x + eps) = log k + x to ~2.5e-4 abs.
#define K3_SPLIT 8
__global__ void __launch_bounds__(256)
final_stream_kernel(float* __restrict__ out)
{
    const int b = blockIdx.x;
    const float4 st = g_stats[b];
    const float invZ = st.y, copy = st.z, invnorm = st.w;
    const float logk = __logf((1.f - copy) * invZ * invnorm);
    const uint4* in8 = (const uint4*)(g_logits + (size_t)b * V_DIM);  // 8 halves each
    float4* out4 = (float4*)(out + (size_t)b * V_DIM);
    const int NV8 = V_DIM / 8;                 // 6250
    const int per = (NV8 + K3_SPLIT - 1) / K3_SPLIT;
    const int beg = blockIdx.y * per;
    const int end = (beg + per < NV8) ? beg + per : NV8;
    for (int i = beg + threadIdx.x; i < end; i += 256) {
        const uint4 u = in8[i];
        const float2 p0 = __half22float2(*(const __half2*)&u.x);
        const float2 p1 = __half22float2(*(const __half2*)&u.y);
        float2 p2 = __half22float2(*(const __half2*)&u.z);
        const float2 p3 = __half22float2(*(const __half2*)&u.w);
        if (i == 0) p2.x = 1e-10f;             // COPY (element 4)
        float4 r0, r1;
        r0.x = logk + p0.x;
        r0.y = logk + p0.y;
        r0.z = logk + p1.x;
        r0.w = logk + p1.y;
        r1.x = logk + p2.x;
        r1.y = logk + p2.y;
        r1.z = logk + p3.x;
        r1.w = logk + p3.y;
        if (i == 0) r0.x = __logf(EPS_F * invnorm + EPS_F);   // PAD (exact)
        out4[2 * i]     = r0;
        out4[2 * i + 1] = r1;
    }
}

// ---------------- K4: scatter fixup (<=128 positions/row, dup-aggregating) --
__global__ void __launch_bounds__(128)
fixup_kernel(float* __restrict__ out)
{
    __shared__ int   stg[S_DIM];
    __shared__ float sad[S_DIM];
    const int b = blockIdx.x, t = threadIdx.x;
    stg[t] = g_tgt[b * S_DIM + t];
    sad[t] = g_addval[b * S_DIM + t];
    __syncthreads();
    const int tg = stg[t];
    if (tg == PAD_IDX) return;
    float tot = 0.f; bool first = true;
    for (int j = 0; j < S_DIM; ++j) {
        if (stg[j] == tg) { tot += sad[j]; if (j < t) first = false; }
    }
    if (!first) return;
    const float4 st = g_stats[b];
    const float l = (tg == COPY_IDX) ? 1e-10f
                                     : __half2float(g_logits[(size_t)b * V_DIM + tg]);
    const float p = (1.f - st.z) * st.y * __expf(l) + tot;
    out[(size_t)b * V_DIM + tg] = __logf(p * st.w + EPS_F);
}

// ---------------- launch ----------------
extern "C" void kernel_launch(void* const* d_in, const int* in_sizes, int n_in,
                              void* d_out, int out_size)
{
    const float* hidden    = (const float*)d_in[0];
    const void*  src       = d_in[1];
    const float* attn      = (const float*)d_in[2];
    const float* W         = (const float*)d_in[3];
    const float* bias      = (const float*)d_in[4];
    const void*  alignment = d_in[5];
    float*       out       = (float*)d_out;

    cudaFuncSetAttribute(gemm_kernel, cudaFuncAttributeMaxDynamicSharedMemorySize, SMEM_BYTES);

    convert_kernel<<<1184, 256>>>(W, hidden);

    dim3 g1(B_DIM / TM, NBLKS);                  // (8, 196) — M fastest for W L2 reuse
    gemm_kernel<<<g1, 256, SMEM_BYTES>>>(bias);

    stats_kernel<<<B_DIM, 256>>>(attn, src, alignment);

    dim3 g3(B_DIM, K3_SPLIT);
    final_stream_kernel<<<g3, 256>>>(out);

    fixup_kernel<<<B_DIM, S_DIM>>>(out);
}